// round 11
// baseline (speedup 1.0000x reference)
#include <cuda_runtime.h>
#include <cuda_fp16.h>
#include <math.h>
#include <stdint.h>

#define N_TOK 32768
#define H_DIM 2048
#define D_DIM 256
#define K_CODE 4096

// ---------------- scratch (static device globals; no runtime allocation) ----------------
__device__ float  g_zf[(size_t)N_TOK * D_DIM];   // pre-projection output (N, D), fp32
__device__ int    g_idx[N_TOK];
__device__ float  g_cnorm[K_CODE];
__device__ double g_cnormd[K_CODE];
__device__ float  g_lse;
__device__ float4 g_tv4[(size_t)N_TOK * 32];     // per (row, chunk): top-4 approx scores
__device__ int4   g_ti4[(size_t)N_TOK * 32];     // per (row, chunk): top-4 code indices
__device__ float  g_loss_part[4096];
__device__ float  g_rate_part[4096];
__device__ int    g_amb_count;
__device__ int    g_amb_rows[N_TOK];

// ---------------- PTX helpers (all sm_80+ generic; no 'a'-suffix features) ----------------
__device__ __forceinline__ uint32_t smem_u32(const void* p) {
    uint32_t a;
    asm("{ .reg .u64 t; cvta.to.shared.u64 t, %1; cvt.u32.u64 %0, t; }" : "=r"(a) : "l"(p));
    return a;
}
__device__ __forceinline__ void ldsm4(uint32_t r[4], uint32_t addr) {
    asm volatile("ldmatrix.sync.aligned.m8n8.x4.shared.b16 {%0,%1,%2,%3}, [%4];"
                 : "=r"(r[0]), "=r"(r[1]), "=r"(r[2]), "=r"(r[3]) : "r"(addr));
}
__device__ __forceinline__ void ldsm2(uint32_t r[2], uint32_t addr) {
    asm volatile("ldmatrix.sync.aligned.m8n8.x2.shared.b16 {%0,%1}, [%2];"
                 : "=r"(r[0]), "=r"(r[1]) : "r"(addr));
}
__device__ __forceinline__ void mma16816(float c[4], const uint32_t a[4], const uint32_t b[2]) {
    asm volatile("mma.sync.aligned.m16n8k16.row.col.f32.f16.f16.f32 "
                 "{%0,%1,%2,%3}, {%4,%5,%6,%7}, {%8,%9}, {%0,%1,%2,%3};"
                 : "+f"(c[0]), "+f"(c[1]), "+f"(c[2]), "+f"(c[3])
                 : "r"(a[0]), "r"(a[1]), "r"(a[2]), "r"(a[3]), "r"(b[0]), "r"(b[1]));
}

// sorted ascending top-4 insert (strict <; ties keep incumbent)
__device__ __forceinline__ void top4_ins(float v[4], int ix[4], float s, int c) {
    if (s >= v[3]) return;
    if (s < v[1]) {
        v[3] = v[2]; ix[3] = ix[2]; v[2] = v[1]; ix[2] = ix[1];
        if (s < v[0]) { v[1] = v[0]; ix[1] = ix[0]; v[0] = s; ix[0] = c; }
        else          { v[1] = s; ix[1] = c; }
    } else {
        if (s < v[2]) { v[3] = v[2]; ix[3] = ix[2]; v[2] = s; ix[2] = c; }
        else          { v[3] = s; ix[3] = c; }
    }
}

// ---------------- tiled split-fp16 GEMM ----------------
// C[128,128] tile = A(128,K) . B(128,K)^T via 2-term fp16 split, 3 products (hh, hl, lh).
// EPI 0: C += bias, store fp32.   EPI 2: distance top-4 per 128-code chunk.
#define LDS_K 40                                  // fp16 elems per smem row (32 + 8 pad)
#define TILE_HB (128 * LDS_K * 2)                 // one operand-term tile: 10240 B
#define STAGE_BYTES (4 * TILE_HB)                 // Ah,Al,Bh,Bl: 40960 B

__device__ __forceinline__ void ldg_tile(float4 v[4], const float* __restrict__ src,
                                         size_t ld, int rbase, int k0, const int* rowmap) {
    int tid = threadIdx.x;
#pragma unroll
    for (int it = 0; it < 4; it++) {
        int slot = tid + it * 256;
        int row = slot >> 3;
        int c4 = (slot & 7) << 2;
        int gr = rowmap ? rowmap[row] : (rbase + row);
        v[it] = *(const float4*)(src + (size_t)gr * ld + (size_t)(k0 + c4));
    }
}
__device__ __forceinline__ void sts_tile(__half* hbuf, __half* lbuf, const float4 v[4]) {
    int tid = threadIdx.x;
#pragma unroll
    for (int it = 0; it < 4; it++) {
        int slot = tid + it * 256;
        int row = slot >> 3;
        int c4 = (slot & 7) << 2;
        float a[4] = {v[it].x, v[it].y, v[it].z, v[it].w};
        __half h[4], l[4];
#pragma unroll
        for (int k = 0; k < 4; k++) {
            h[k] = __float2half_rn(a[k]);
            l[k] = __float2half_rn(a[k] - __half2float(h[k]));
        }
        *(uint2*)(hbuf + row * LDS_K + c4) = *(const uint2*)h;
        *(uint2*)(lbuf + row * LDS_K + c4) = *(const uint2*)l;
    }
}

__device__ __forceinline__ void compute_product(const __half* Ab, const __half* Bb,
                                                float acc[4][4][4], int wm, int wn, int lane) {
#pragma unroll
    for (int kk = 0; kk < 32; kk += 16) {
        uint32_t af[4][4], bf[4][2];
        int arow = wm * 64 + (lane & 15);
        int acol = kk + ((lane >> 4) << 3);
#pragma unroll
        for (int ms = 0; ms < 4; ms++)
            ldsm4(af[ms], smem_u32(Ab + (size_t)(arow + ms * 16) * LDS_K + acol));
        int brow = wn * 32 + (lane & 7);
        int bcol = kk + (((lane >> 3) & 1) << 3);
#pragma unroll
        for (int ns = 0; ns < 4; ns++)
            ldsm2(bf[ns], smem_u32(Bb + (size_t)(brow + ns * 8) * LDS_K + bcol));
#pragma unroll
        for (int ms = 0; ms < 4; ms++)
#pragma unroll
            for (int ns = 0; ns < 4; ns++)
                mma16816(acc[ms][ns], af[ms], bf[ns]);
    }
}

template<int EPI>
__global__ __launch_bounds__(256) void gemm_mm(
    const float* __restrict__ A, const float* __restrict__ B,
    size_t lda, size_t ldb, int nch,
    const float* __restrict__ bias, float* __restrict__ C, size_t ldc,
    const int* __restrict__ aidx)
{
    extern __shared__ char smem[];
    __shared__ int rowmap[128];
    int tid = threadIdx.x, lane = tid & 31, wid = tid >> 5;
    int wm = wid >> 2, wn = wid & 3;
    int row0 = blockIdx.y * 128, col0 = blockIdx.x * 128;

    if (aidx) {
        if (tid < 128) rowmap[tid] = aidx[row0 + tid];
        __syncthreads();
    }
    const int* rm = aidx ? rowmap : nullptr;

    float acc[4][4][4];
#pragma unroll
    for (int i = 0; i < 4; i++)
#pragma unroll
        for (int j = 0; j < 4; j++)
#pragma unroll
            for (int k = 0; k < 4; k++) acc[i][j][k] = 0.f;

    float4 pa[4], pb[4];
    ldg_tile(pa, A, lda, row0, 0, rm);
    ldg_tile(pb, B, ldb, col0, 0, nullptr);
    {
        __half* Ah = (__half*)smem;
        sts_tile(Ah, Ah + 128 * LDS_K, pa);
        __half* Bh = (__half*)(smem + 2 * TILE_HB);
        sts_tile(Bh, Bh + 128 * LDS_K, pb);
    }
    __syncthreads();

    for (int c = 0; c < nch; c++) {
        int s = c & 1;
        char* buf = smem + s * STAGE_BYTES;
        if (c + 1 < nch) {
            ldg_tile(pa, A, lda, row0, (c + 1) * 32, rm);
            ldg_tile(pb, B, ldb, col0, (c + 1) * 32, nullptr);
        }
        const __half* Ah = (const __half*)buf;
        const __half* Al = Ah + 128 * LDS_K;
        const __half* Bh = (const __half*)(buf + 2 * TILE_HB);
        const __half* Bl = Bh + 128 * LDS_K;
        compute_product(Ah, Bh, acc, wm, wn, lane);   // hi * hi
        compute_product(Ah, Bl, acc, wm, wn, lane);   // hi * lo
        compute_product(Al, Bh, acc, wm, wn, lane);   // lo * hi
        if (c + 1 < nch) {
            char* nb = smem + (s ^ 1) * STAGE_BYTES;
            __half* nAh = (__half*)nb;
            sts_tile(nAh, nAh + 128 * LDS_K, pa);
            __half* nBh = (__half*)(nb + 2 * TILE_HB);
            sts_tile(nBh, nBh + 128 * LDS_K, pb);
        }
        __syncthreads();
    }

    int g = lane >> 2, q = lane & 3;
    if (EPI == 0) {
#pragma unroll
        for (int ms = 0; ms < 4; ms++)
#pragma unroll
            for (int ns = 0; ns < 4; ns++)
#pragma unroll
                for (int i = 0; i < 2; i++) {
                    int r = wm * 64 + ms * 16 + i * 8 + g;
                    int cc = wn * 32 + ns * 8 + q * 2;
                    float2 v;
                    v.x = acc[ms][ns][2 * i]     + bias[col0 + cc];
                    v.y = acc[ms][ns][2 * i + 1] + bias[col0 + cc + 1];
                    *(float2*)(C + (size_t)(row0 + r) * ldc + col0 + cc) = v;
                }
    } else {
        // distance epilogue: sc = cnorm - 2*dot; per-row top-4 over this 128-code chunk
        float* s_v = (float*)smem;            // 128 rows x 16 entries
        int*   s_i = (int*)(smem + 128 * 16 * 4);
#pragma unroll
        for (int ms = 0; ms < 4; ms++)
#pragma unroll
            for (int i = 0; i < 2; i++) {
                float tv[4] = {3.4e38f, 3.4e38f, 3.4e38f, 3.4e38f};
                int tix[4] = {0x7fffffff, 0x7fffffff, 0x7fffffff, 0x7fffffff};
#pragma unroll
                for (int ns = 0; ns < 4; ns++)
#pragma unroll
                    for (int j = 0; j < 2; j++) {
                        int code = col0 + wn * 32 + ns * 8 + q * 2 + j;
                        float sc = __ldg(&g_cnorm[code]) - 2.0f * acc[ms][ns][2 * i + j];
                        top4_ins(tv, tix, sc, code);
                    }
#pragma unroll
                for (int o = 1; o <= 2; o <<= 1) {
                    float ov[4]; int oix[4];
#pragma unroll
                    for (int t = 0; t < 4; t++) {
                        ov[t]  = __shfl_xor_sync(0xffffffffu, tv[t], o);
                        oix[t] = __shfl_xor_sync(0xffffffffu, tix[t], o);
                    }
#pragma unroll
                    for (int t = 0; t < 4; t++) top4_ins(tv, tix, ov[t], oix[t]);
                }
                if (q == 0) {
                    int r = wm * 64 + ms * 16 + i * 8 + g;
#pragma unroll
                    for (int t = 0; t < 4; t++) {
                        s_v[r * 16 + wn * 4 + t] = tv[t];
                        s_i[r * 16 + wn * 4 + t] = tix[t];
                    }
                }
            }
        __syncthreads();
        if (tid < 128) {
            float tv[4] = {3.4e38f, 3.4e38f, 3.4e38f, 3.4e38f};
            int tix[4] = {0x7fffffff, 0x7fffffff, 0x7fffffff, 0x7fffffff};
#pragma unroll
            for (int w = 0; w < 4; w++)
#pragma unroll
                for (int t = 0; t < 4; t++)
                    top4_ins(tv, tix, s_v[tid * 16 + w * 4 + t], s_i[tid * 16 + w * 4 + t]);
            size_t o = (size_t)(row0 + tid) * 32 + blockIdx.x;
            g_tv4[o] = make_float4(tv[0], tv[1], tv[2], tv[3]);
            g_ti4[o] = make_int4(tix[0], tix[1], tix[2], tix[3]);
        }
    }
}

// ---------------- codebook squared norms (fp32 + fp64) + ambiguity counter reset ----------------
__global__ void cnorm_kernel(const float* __restrict__ cb) {
    if (blockIdx.x == 0 && threadIdx.x == 0) g_amb_count = 0;
    int code = blockIdx.x * 8 + (threadIdx.x >> 5);
    int lane = threadIdx.x & 31;
    const float* row = cb + (size_t)code * D_DIM;
    double s = 0.0;
#pragma unroll
    for (int d = lane; d < D_DIM; d += 32) { double v = (double)row[d]; s += v * v; }
#pragma unroll
    for (int o = 16; o; o >>= 1) s += __shfl_xor_sync(0xffffffffu, s, o);
    if (lane == 0) { g_cnormd[code] = s; g_cnorm[code] = (float)s; }
}

// ---------------- logsumexp of prior logits ----------------
__global__ void lse_kernel(const float* __restrict__ pl) {
    __shared__ float red[1024];
    int tid = threadIdx.x;
    float m = -1e30f;
    for (int i = tid; i < K_CODE; i += 1024) m = fmaxf(m, pl[i]);
    red[tid] = m; __syncthreads();
    for (int s = 512; s; s >>= 1) { if (tid < s) red[tid] = fmaxf(red[tid], red[tid + s]); __syncthreads(); }
    m = red[0]; __syncthreads();
    float sum = 0.f;
    for (int i = tid; i < K_CODE; i += 1024) sum += expf(pl[i] - m);
    red[tid] = sum; __syncthreads();
    for (int s = 512; s; s >>= 1) { if (tid < s) red[tid] += red[tid + s]; __syncthreads(); }
    if (tid == 0) g_lse = m + logf(red[0]);
}

// ---------------- fp64 argmin rescue + ambiguity flag + loss/rate partials ----------------
__global__ void rescue_kernel(const float* __restrict__ cb, const float* __restrict__ prior,
                              float* __restrict__ out_idx, int wr) {
    __shared__ float shl[8], shr[8];
    int w = threadIdx.x >> 5, lane = threadIdx.x & 31;
    int row = blockIdx.x * 8 + w;
    size_t ob = (size_t)row * 32 + lane;
    float4 tv = g_tv4[ob];
    int4  tix = g_ti4[ob];
    float amin = tv.x;
#pragma unroll
    for (int o = 16; o; o >>= 1) amin = fminf(amin, __shfl_xor_sync(0xffffffffu, amin, o));
    float thr = amin + 0.25f;

    float zreg[8];
#pragma unroll
    for (int k = 0; k < 8; k++) zreg[k] = g_zf[(size_t)row * D_DIM + k * 32 + lane];

    double bv = 1e300, sv = 1e300; int bi = 0x7fffffff;
    for (int c = 0; c < 128; c++) {
        int lsrc = c >> 2, s = c & 3;
        float av = __shfl_sync(0xffffffffu, s == 0 ? tv.x : s == 1 ? tv.y : s == 2 ? tv.z : tv.w, lsrc);
        int  ix  = __shfl_sync(0xffffffffu, s == 0 ? tix.x : s == 1 ? tix.y : s == 2 ? tix.z : tix.w, lsrc);
        if (av > thr) continue;                          // warp-uniform (broadcast values)
        const float* cr = cb + (size_t)ix * D_DIM;
        double sd = 0.0;
#pragma unroll
        for (int k = 0; k < 8; k++) sd += (double)zreg[k] * (double)cr[k * 32 + lane];
#pragma unroll
        for (int o = 16; o; o >>= 1) sd += __shfl_xor_sync(0xffffffffu, sd, o);
        double sc = g_cnormd[ix] - 2.0 * sd;
        if (sc < bv || (sc == bv && ix < bi)) { sv = bv; bv = sc; bi = ix; }
        else if (sc < sv) sv = sc;
    }

    // flag ambiguous rows (top-2 gap below 0.02) for exact fp64-z re-resolution
    if (lane == 0 && (sv - bv) < 0.02) {
        int pos = atomicAdd(&g_amb_count, 1);
        g_amb_rows[pos] = row;
    }

    const float* cr = cb + (size_t)bi * D_DIM;
    float s2 = 0.f;
#pragma unroll
    for (int k = 0; k < 8; k++) { float d = cr[k * 32 + lane] - zreg[k]; s2 += d * d; }
#pragma unroll
    for (int o = 16; o; o >>= 1) s2 += __shfl_xor_sync(0xffffffffu, s2, o);
    if (lane == 0) {
        g_idx[row] = bi;
        if (wr) out_idx[row] = (float)bi;
        shl[w] = s2;
        shr[w] = g_lse - prior[bi];
    }
    __syncthreads();
    if (threadIdx.x == 0) {
        float a = 0.f, b = 0.f;
#pragma unroll
        for (int k = 0; k < 8; k++) { a += shl[k]; b += shr[k]; }
        g_loss_part[blockIdx.x] = a;
        g_rate_part[blockIdx.x] = b;
    }
}

// ---------------- exact resolver: fp64 z from inputs for ambiguous rows ----------------
__global__ __launch_bounds__(256) void exact_fix_kernel(
    const float* __restrict__ embed, const float* __restrict__ pre_w,
    const float* __restrict__ pre_b, const float* __restrict__ cb,
    float* __restrict__ out_idx, int wr)
{
    __shared__ float  es[H_DIM];
    __shared__ double zs[D_DIM];
    __shared__ float  cand_v[128];
    __shared__ int    cand_i[128];
    __shared__ float  s_amin;
    __shared__ double wv[8];
    __shared__ int    wi[8];
    int tid = threadIdx.x, lane = tid & 31, wid = tid >> 5;
    int nab = g_amb_count;

    for (int it = blockIdx.x; it < nab; it += gridDim.x) {
        int row = g_amb_rows[it];
        // load embed row
        for (int k = tid; k < H_DIM; k += 256) es[k] = embed[(size_t)row * H_DIM + k];
        // candidate list for this row
        if (tid < 32) {
            float4 tv = g_tv4[(size_t)row * 32 + tid];
            int4  ti  = g_ti4[(size_t)row * 32 + tid];
            cand_v[tid * 4 + 0] = tv.x; cand_i[tid * 4 + 0] = ti.x;
            cand_v[tid * 4 + 1] = tv.y; cand_i[tid * 4 + 1] = ti.y;
            cand_v[tid * 4 + 2] = tv.z; cand_i[tid * 4 + 2] = ti.z;
            cand_v[tid * 4 + 3] = tv.w; cand_i[tid * 4 + 3] = ti.w;
            float m = tv.x;
#pragma unroll
            for (int o = 16; o; o >>= 1) m = fminf(m, __shfl_xor_sync(0xffffffffu, m, o));
            if (tid == 0) s_amin = m;
        }
        __syncthreads();
        // exact fp64 z: thread d computes z[d]
        {
            const float* wrow = pre_w + (size_t)tid * H_DIM;
            double s = (double)pre_b[tid];
            for (int k = 0; k < H_DIM; k++) s += (double)es[k] * (double)wrow[k];
            zs[tid] = s;
        }
        __syncthreads();
        // exact fp64 scoring of candidates within threshold
        float thr = s_amin + 0.25f;
        double bv = 1e300; int bi = 0x7fffffff;
        for (int j = wid; j < 128; j += 8) {
            if (cand_v[j] > thr) continue;
            int code = cand_i[j];
            const float* cr = cb + (size_t)code * D_DIM;
            double s = 0.0;
#pragma unroll
            for (int k = 0; k < 8; k++) s += zs[k * 32 + lane] * (double)cr[k * 32 + lane];
#pragma unroll
            for (int o = 16; o; o >>= 1) s += __shfl_xor_sync(0xffffffffu, s, o);
            double sc = g_cnormd[code] - 2.0 * s;
            if (sc < bv || (sc == bv && code < bi)) { bv = sc; bi = code; }
        }
        if (lane == 0) { wv[wid] = bv; wi[wid] = bi; }
        __syncthreads();
        if (tid == 0) {
            double fbv = 1e300; int fbi = 0x7fffffff;
#pragma unroll
            for (int k = 0; k < 8; k++) {
                if (wv[k] < fbv || (wv[k] == fbv && wi[k] < fbi)) { fbv = wv[k]; fbi = wi[k]; }
            }
            g_idx[row] = fbi;
            if (wr) out_idx[row] = (float)fbi;
        }
        __syncthreads();
    }
}

__global__ void final_kernel(float* __restrict__ out, int wr) {
    __shared__ float rl[1024], rr[1024];
    int t = threadIdx.x;
    float a = 0.f, b = 0.f;
    for (int k = t; k < 4096; k += 1024) { a += g_loss_part[k]; b += g_rate_part[k]; }
    rl[t] = a; rr[t] = b; __syncthreads();
    for (int s = 512; s; s >>= 1) {
        if (t < s) { rl[t] += rl[t + s]; rr[t] += rr[t + s]; }
        __syncthreads();
    }
    if (t == 0 && wr) {
        out[0] = rr[0] / 0.69314718055994530942f;
        out[1] = 1.25f * rl[0] / (float)((size_t)N_TOK * D_DIM);
    }
}

// ---------------- host launcher ----------------
extern "C" void kernel_launch(void* const* d_in, const int* in_sizes, int n_in,
                              void* d_out, int out_size) {
    const float* embed  = (const float*)d_in[0];
    const float* pre_w  = (const float*)d_in[1];
    const float* pre_b  = (const float*)d_in[2];
    const float* cb     = (const float*)d_in[3];
    const float* post_w = (const float*)d_in[4];
    const float* post_b = (const float*)d_in[5];
    const float* prior  = (const float*)d_in[6];
    float* out = (float*)d_out;

    float* zptr; cudaGetSymbolAddress((void**)&zptr, g_zf);
    int*   iptr; cudaGetSymbolAddress((void**)&iptr, g_idx);

    const int SMEM = 2 * STAGE_BYTES;   // 81920 B
    cudaFuncSetAttribute(gemm_mm<0>, cudaFuncAttributeMaxDynamicSharedMemorySize, SMEM);
    cudaFuncSetAttribute(gemm_mm<2>, cudaFuncAttributeMaxDynamicSharedMemorySize, SMEM);

    cnorm_kernel<<<K_CODE / 8, 256>>>(cb);
    lse_kernel<<<1, 1024>>>(prior);

    // GEMM1: z = embed @ pre_w^T + pre_b   (M=32768, N=256, K=2048)
    gemm_mm<0><<<dim3(D_DIM / 128, N_TOK / 128), 256, SMEM>>>(
        embed, pre_w, H_DIM, H_DIM, H_DIM / 32, pre_b, zptr, D_DIM, nullptr);

    // distances: per-chunk top-4 of ||c||^2 - 2 z.c   (M=32768, N=4096, K=256)
    gemm_mm<2><<<dim3(K_CODE / 128, N_TOK / 128), 256, SMEM>>>(
        zptr, cb, D_DIM, D_DIM, D_DIM / 32, nullptr, nullptr, 0, nullptr);

    long long need = (long long)N_TOK * H_DIM + N_TOK + 2;
    int full = ((long long)out_size >= need) ? 1 : 0;

    // fp64 argmin on z~ + ambiguity flags + loss/rate partials + index output
    rescue_kernel<<<N_TOK / 8, 256>>>(cb, prior, out + (size_t)N_TOK * H_DIM, full);

    // exact fp64-z re-resolution for ambiguous rows (corrects g_idx before GEMM3)
    exact_fix_kernel<<<256, 256>>>(embed, pre_w, pre_b, cb, out + (size_t)N_TOK * H_DIM, full);

    // GEMM3: embed_hat = codebook[idx] @ post_w^T + post_b  (M=32768, N=2048, K=256)
    gemm_mm<0><<<dim3(H_DIM / 128, N_TOK / 128), 256, SMEM>>>(
        cb, post_w, D_DIM, D_DIM, D_DIM / 32, post_b, out, H_DIM, iptr);

    final_kernel<<<1, 1024>>>(out + (size_t)N_TOK * H_DIM + N_TOK, full);
}

// round 14
// speedup vs baseline: 1.7537x; 1.7537x over previous
#include <cuda_runtime.h>
#include <cuda_fp16.h>
#include <math.h>
#include <stdint.h>

#define N_TOK 32768
#define H_DIM 2048
#define D_DIM 256
#define K_CODE 4096

// ---------------- scratch (static device globals; no runtime allocation) ----------------
__device__ __align__(128) __half g_ehi[(size_t)N_TOK * H_DIM];
__device__ __align__(128) __half g_elo[(size_t)N_TOK * H_DIM];
__device__ __align__(128) __half g_pwhi[(size_t)D_DIM * H_DIM];
__device__ __align__(128) __half g_pwlo[(size_t)D_DIM * H_DIM];
__device__ __align__(128) __half g_cbhi[(size_t)K_CODE * D_DIM];
__device__ __align__(128) __half g_cblo[(size_t)K_CODE * D_DIM];
__device__ __align__(128) __half g_pohi[(size_t)H_DIM * D_DIM];
__device__ __align__(128) __half g_polo[(size_t)H_DIM * D_DIM];
__device__ __align__(128) __half g_zhi[(size_t)N_TOK * D_DIM];
__device__ __align__(128) __half g_zlo[(size_t)N_TOK * D_DIM];
__device__ __align__(128) float  g_zf[(size_t)N_TOK * D_DIM];
__device__ int    g_idx[N_TOK];
__device__ float  g_cnorm[K_CODE];
__device__ double g_cnormd[K_CODE];
__device__ float  g_lse;
__device__ float4 g_tv4[(size_t)N_TOK * 32];
__device__ int4   g_ti4[(size_t)N_TOK * 32];
__device__ float  g_loss_part[4096];
__device__ float  g_rate_part[4096];
__device__ int    g_amb_count;
__device__ int    g_amb_rows[N_TOK];

// ---------------- PTX helpers (all sm_80+ generic; no 'a'-suffix features) ----------------
__device__ __forceinline__ uint32_t smem_u32(const void* p) {
    uint32_t a;
    asm("{ .reg .u64 t; cvta.to.shared.u64 t, %1; cvt.u32.u64 %0, t; }" : "=r"(a) : "l"(p));
    return a;
}
__device__ __forceinline__ void ldsm4(uint32_t r[4], uint32_t addr) {
    asm volatile("ldmatrix.sync.aligned.m8n8.x4.shared.b16 {%0,%1,%2,%3}, [%4];"
                 : "=r"(r[0]), "=r"(r[1]), "=r"(r[2]), "=r"(r[3]) : "r"(addr));
}
__device__ __forceinline__ void ldsm2(uint32_t r[2], uint32_t addr) {
    asm volatile("ldmatrix.sync.aligned.m8n8.x2.shared.b16 {%0,%1}, [%2];"
                 : "=r"(r[0]), "=r"(r[1]) : "r"(addr));
}
__device__ __forceinline__ void mma16816(float c[4], const uint32_t a[4], const uint32_t b[2]) {
    asm volatile("mma.sync.aligned.m16n8k16.row.col.f32.f16.f16.f32 "
                 "{%0,%1,%2,%3}, {%4,%5,%6,%7}, {%8,%9}, {%0,%1,%2,%3};"
                 : "+f"(c[0]), "+f"(c[1]), "+f"(c[2]), "+f"(c[3])
                 : "r"(a[0]), "r"(a[1]), "r"(a[2]), "r"(a[3]), "r"(b[0]), "r"(b[1]));
}
#define CP16(dst, src) \
    asm volatile("cp.async.cg.shared.global [%0], [%1], 16;" :: "r"(dst), "l"(src))
#define CP_COMMIT() asm volatile("cp.async.commit_group;" ::: "memory")
#define CP_WAIT(n)  asm volatile("cp.async.wait_group %0;" :: "n"(n) : "memory")

// sorted ascending top-4 insert (strict <; ties keep incumbent)
__device__ __forceinline__ void top4_ins(float v[4], int ix[4], float s, int c) {
    if (s >= v[3]) return;
    if (s < v[1]) {
        v[3] = v[2]; ix[3] = ix[2]; v[2] = v[1]; ix[2] = ix[1];
        if (s < v[0]) { v[1] = v[0]; ix[1] = ix[0]; v[0] = s; ix[0] = c; }
        else          { v[1] = s; ix[1] = c; }
    } else {
        if (s < v[2]) { v[3] = v[2]; ix[3] = ix[2]; v[2] = s; ix[2] = c; }
        else          { v[3] = s; ix[3] = c; }
    }
}

// ---------------- tiled split-fp16 GEMM (pre-split operands, cp.async pipeline) ----------------
#define LDS_K 40                                  // fp16 elems per smem row (32 + 8 pad)
#define TILE_HB (128 * LDS_K * 2)                 // one operand-term tile: 10240 B
#define STAGE_BYTES (4 * TILE_HB)                 // Ah,Al,Bh,Bl: 40960 B

// async-load one [128 x 32] half tile (row stride ld halves) into padded smem tile
__device__ __forceinline__ void load_tile_async(char* dst, const __half* __restrict__ src,
                                                size_t ld, int rbase, int k0, const int* rowmap) {
    int tid = threadIdx.x;
#pragma unroll
    for (int it = 0; it < 2; it++) {
        int slot = tid + it * 256;        // 512 slots = 128 rows x 4 x 16B
        int row = slot >> 2;
        int c16 = slot & 3;
        int gr = rowmap ? rowmap[row] : (rbase + row);
        const __half* s = src + (size_t)gr * ld + (size_t)(k0 + c16 * 8);
        uint32_t d = smem_u32(dst + row * (LDS_K * 2) + c16 * 16);
        CP16(d, s);
    }
}

__device__ __forceinline__ void compute_product(const __half* Ab, const __half* Bb,
                                                float acc[4][4][4], int wm, int wn, int lane) {
#pragma unroll
    for (int kk = 0; kk < 32; kk += 16) {
        uint32_t af[4][4], bf[4][2];
        int arow = wm * 64 + (lane & 15);
        int acol = kk + ((lane >> 4) << 3);
#pragma unroll
        for (int ms = 0; ms < 4; ms++)
            ldsm4(af[ms], smem_u32(Ab + (size_t)(arow + ms * 16) * LDS_K + acol));
        int brow = wn * 32 + (lane & 7);
        int bcol = kk + (((lane >> 3) & 1) << 3);
#pragma unroll
        for (int ns = 0; ns < 4; ns++)
            ldsm2(bf[ns], smem_u32(Bb + (size_t)(brow + ns * 8) * LDS_K + bcol));
#pragma unroll
        for (int ms = 0; ms < 4; ms++)
#pragma unroll
            for (int ns = 0; ns < 4; ns++)
                mma16816(acc[ms][ns], af[ms], bf[ns]);
    }
}

// EPI 0: C = acc + bias (fp32).  EPI 1: also emit z hi/lo halves.  EPI 2: distance top-4 per chunk.
template<int EPI>
__global__ __launch_bounds__(256, 2) void gemm_mm(
    const __half* __restrict__ Ahi, const __half* __restrict__ Alo,
    const __half* __restrict__ Bhi, const __half* __restrict__ Blo,
    size_t lda, size_t ldb, int nch,
    const float* __restrict__ bias, float* __restrict__ C, size_t ldc,
    const int* __restrict__ aidx)
{
    extern __shared__ char smem[];
    __shared__ int rowmap[128];
    int tid = threadIdx.x, lane = tid & 31, wid = tid >> 5;
    int wm = wid >> 2, wn = wid & 3;
    int row0 = blockIdx.y * 128, col0 = blockIdx.x * 128;

    if (aidx) {
        if (tid < 128) rowmap[tid] = aidx[row0 + tid];
        __syncthreads();
    }
    const int* rm = aidx ? rowmap : nullptr;

    float acc[4][4][4];
#pragma unroll
    for (int i = 0; i < 4; i++)
#pragma unroll
        for (int j = 0; j < 4; j++)
#pragma unroll
            for (int k = 0; k < 4; k++) acc[i][j][k] = 0.f;

    // prologue: stage 0
    {
        char* b0 = smem;
        load_tile_async(b0,               Ahi, lda, row0, 0, rm);
        load_tile_async(b0 + TILE_HB,     Alo, lda, row0, 0, rm);
        load_tile_async(b0 + 2 * TILE_HB, Bhi, ldb, col0, 0, nullptr);
        load_tile_async(b0 + 3 * TILE_HB, Blo, ldb, col0, 0, nullptr);
        CP_COMMIT();
    }

    for (int c = 0; c < nch; c++) {
        int s = c & 1;
        char* buf = smem + s * STAGE_BYTES;
        if (c + 1 < nch) {
            char* nb = smem + (s ^ 1) * STAGE_BYTES;
            int k0 = (c + 1) * 32;
            load_tile_async(nb,               Ahi, lda, row0, k0, rm);
            load_tile_async(nb + TILE_HB,     Alo, lda, row0, k0, rm);
            load_tile_async(nb + 2 * TILE_HB, Bhi, ldb, col0, k0, nullptr);
            load_tile_async(nb + 3 * TILE_HB, Blo, ldb, col0, k0, nullptr);
            CP_COMMIT();
            CP_WAIT(1);
        } else {
            CP_WAIT(0);
        }
        __syncthreads();
        const __half* Ah = (const __half*)buf;
        const __half* Al = (const __half*)(buf + TILE_HB);
        const __half* Bh = (const __half*)(buf + 2 * TILE_HB);
        const __half* Bl = (const __half*)(buf + 3 * TILE_HB);
        compute_product(Ah, Bh, acc, wm, wn, lane);   // hi * hi
        compute_product(Ah, Bl, acc, wm, wn, lane);   // hi * lo
        compute_product(Al, Bh, acc, wm, wn, lane);   // lo * hi
        __syncthreads();
    }

    int g = lane >> 2, q = lane & 3;
    if (EPI == 0 || EPI == 1) {
#pragma unroll
        for (int ms = 0; ms < 4; ms++)
#pragma unroll
            for (int ns = 0; ns < 4; ns++)
#pragma unroll
                for (int i = 0; i < 2; i++) {
                    int r = wm * 64 + ms * 16 + i * 8 + g;
                    int cc = wn * 32 + ns * 8 + q * 2;
                    float2 v;
                    v.x = acc[ms][ns][2 * i]     + bias[col0 + cc];
                    v.y = acc[ms][ns][2 * i + 1] + bias[col0 + cc + 1];
                    *(float2*)(C + (size_t)(row0 + r) * ldc + col0 + cc) = v;
                    if (EPI == 1) {
                        size_t base = (size_t)(row0 + r) * D_DIM + col0 + cc;
                        __half h0 = __float2half_rn(v.x);
                        __half h1 = __float2half_rn(v.y);
                        __half l0 = __float2half_rn(v.x - __half2float(h0));
                        __half l1 = __float2half_rn(v.y - __half2float(h1));
                        __half hh[2] = {h0, h1}, ll[2] = {l0, l1};
                        *(uint32_t*)(g_zhi + base) = *(uint32_t*)hh;
                        *(uint32_t*)(g_zlo + base) = *(uint32_t*)ll;
                    }
                }
    } else {
        // distance epilogue: sc = cnorm - 2*dot; per-row top-4 over this 128-code chunk
        float* s_v = (float*)smem;            // 128 rows x 16 entries
        int*   s_i = (int*)(smem + 128 * 16 * 4);
#pragma unroll
        for (int ms = 0; ms < 4; ms++)
#pragma unroll
            for (int i = 0; i < 2; i++) {
                float tv[4] = {3.4e38f, 3.4e38f, 3.4e38f, 3.4e38f};
                int tix[4] = {0x7fffffff, 0x7fffffff, 0x7fffffff, 0x7fffffff};
#pragma unroll
                for (int ns = 0; ns < 4; ns++)
#pragma unroll
                    for (int j = 0; j < 2; j++) {
                        int code = col0 + wn * 32 + ns * 8 + q * 2 + j;
                        float sc = __ldg(&g_cnorm[code]) - 2.0f * acc[ms][ns][2 * i + j];
                        top4_ins(tv, tix, sc, code);
                    }
#pragma unroll
                for (int o = 1; o <= 2; o <<= 1) {
                    float ov[4]; int oix[4];
#pragma unroll
                    for (int t = 0; t < 4; t++) {
                        ov[t]  = __shfl_xor_sync(0xffffffffu, tv[t], o);
                        oix[t] = __shfl_xor_sync(0xffffffffu, tix[t], o);
                    }
#pragma unroll
                    for (int t = 0; t < 4; t++) top4_ins(tv, tix, ov[t], oix[t]);
                }
                if (q == 0) {
                    int r = wm * 64 + ms * 16 + i * 8 + g;
#pragma unroll
                    for (int t = 0; t < 4; t++) {
                        s_v[r * 16 + wn * 4 + t] = tv[t];
                        s_i[r * 16 + wn * 4 + t] = tix[t];
                    }
                }
            }
        __syncthreads();
        if (tid < 128) {
            float tv[4] = {3.4e38f, 3.4e38f, 3.4e38f, 3.4e38f};
            int tix[4] = {0x7fffffff, 0x7fffffff, 0x7fffffff, 0x7fffffff};
#pragma unroll
            for (int w = 0; w < 4; w++)
#pragma unroll
                for (int t = 0; t < 4; t++)
                    top4_ins(tv, tix, s_v[tid * 16 + w * 4 + t], s_i[tid * 16 + w * 4 + t]);
            size_t o = (size_t)(row0 + tid) * 32 + blockIdx.x;
            g_tv4[o] = make_float4(tv[0], tv[1], tv[2], tv[3]);
            g_ti4[o] = make_int4(tix[0], tix[1], tix[2], tix[3]);
        }
    }
}

// ---------------- split preconversion (fp32 -> hi/lo fp16) ----------------
__global__ void split2h_kernel(const float* __restrict__ x, __half* __restrict__ h,
                               __half* __restrict__ l, int n4) {
    int i = blockIdx.x * 256 + threadIdx.x;
    if (i >= n4) return;
    float4 v = ((const float4*)x)[i];
    float a[4] = {v.x, v.y, v.z, v.w};
    __half hh[4], ll[4];
#pragma unroll
    for (int k = 0; k < 4; k++) {
        hh[k] = __float2half_rn(a[k]);
        ll[k] = __float2half_rn(a[k] - __half2float(hh[k]));
    }
    ((uint2*)h)[i] = *(uint2*)hh;
    ((uint2*)l)[i] = *(uint2*)ll;
}

// ---------------- codebook squared norms (fp32 + fp64) + ambiguity counter reset ----------------
__global__ void cnorm_kernel(const float* __restrict__ cb) {
    if (blockIdx.x == 0 && threadIdx.x == 0) g_amb_count = 0;
    int code = blockIdx.x * 8 + (threadIdx.x >> 5);
    int lane = threadIdx.x & 31;
    const float* row = cb + (size_t)code * D_DIM;
    double s = 0.0;
#pragma unroll
    for (int d = lane; d < D_DIM; d += 32) { double v = (double)row[d]; s += v * v; }
#pragma unroll
    for (int o = 16; o; o >>= 1) s += __shfl_xor_sync(0xffffffffu, s, o);
    if (lane == 0) { g_cnormd[code] = s; g_cnorm[code] = (float)s; }
}

// ---------------- logsumexp of prior logits ----------------
__global__ void lse_kernel(const float* __restrict__ pl) {
    __shared__ float red[1024];
    int tid = threadIdx.x;
    float m = -1e30f;
    for (int i = tid; i < K_CODE; i += 1024) m = fmaxf(m, pl[i]);
    red[tid] = m; __syncthreads();
    for (int s = 512; s; s >>= 1) { if (tid < s) red[tid] = fmaxf(red[tid], red[tid + s]); __syncthreads(); }
    m = red[0]; __syncthreads();
    float sum = 0.f;
    for (int i = tid; i < K_CODE; i += 1024) sum += expf(pl[i] - m);
    red[tid] = sum; __syncthreads();
    for (int s = 512; s; s >>= 1) { if (tid < s) red[tid] += red[tid + s]; __syncthreads(); }
    if (tid == 0) g_lse = m + logf(red[0]);
}

// ---------------- fp64 argmin rescue + ambiguity flag + loss/rate partials ----------------
__global__ void rescue_kernel(const float* __restrict__ cb, const float* __restrict__ prior,
                              float* __restrict__ out_idx, int wr) {
    __shared__ float shl[8], shr[8];
    int w = threadIdx.x >> 5, lane = threadIdx.x & 31;
    int row = blockIdx.x * 8 + w;
    size_t ob = (size_t)row * 32 + lane;
    float4 tv = g_tv4[ob];
    int4  tix = g_ti4[ob];
    float amin = tv.x;
#pragma unroll
    for (int o = 16; o; o >>= 1) amin = fminf(amin, __shfl_xor_sync(0xffffffffu, amin, o));
    float thr = amin + 0.25f;

    float zreg[8];
#pragma unroll
    for (int k = 0; k < 8; k++) zreg[k] = g_zf[(size_t)row * D_DIM + k * 32 + lane];

    double bv = 1e300, sv = 1e300; int bi = 0x7fffffff;
    for (int c = 0; c < 128; c++) {
        int lsrc = c >> 2, s = c & 3;
        float av = __shfl_sync(0xffffffffu, s == 0 ? tv.x : s == 1 ? tv.y : s == 2 ? tv.z : tv.w, lsrc);
        int  ix  = __shfl_sync(0xffffffffu, s == 0 ? tix.x : s == 1 ? tix.y : s == 2 ? tix.z : tix.w, lsrc);
        if (av > thr) continue;                          // warp-uniform (broadcast values)
        const float* cr = cb + (size_t)ix * D_DIM;
        double sd = 0.0;
#pragma unroll
        for (int k = 0; k < 8; k++) sd += (double)zreg[k] * (double)cr[k * 32 + lane];
#pragma unroll
        for (int o = 16; o; o >>= 1) sd += __shfl_xor_sync(0xffffffffu, sd, o);
        double sc = g_cnormd[ix] - 2.0 * sd;
        if (sc < bv || (sc == bv && ix < bi)) { sv = bv; bv = sc; bi = ix; }
        else if (sc < sv) sv = sc;
    }

    // flag ambiguous rows (top-2 gap below 0.02) for exact fp64-z re-resolution
    if (lane == 0 && (sv - bv) < 0.02) {
        int pos = atomicAdd(&g_amb_count, 1);
        g_amb_rows[pos] = row;
    }

    const float* cr = cb + (size_t)bi * D_DIM;
    float s2 = 0.f;
#pragma unroll
    for (int k = 0; k < 8; k++) { float d = cr[k * 32 + lane] - zreg[k]; s2 += d * d; }
#pragma unroll
    for (int o = 16; o; o >>= 1) s2 += __shfl_xor_sync(0xffffffffu, s2, o);
    if (lane == 0) {
        g_idx[row] = bi;
        if (wr) out_idx[row] = (float)bi;
        shl[w] = s2;
        shr[w] = g_lse - prior[bi];
    }
    __syncthreads();
    if (threadIdx.x == 0) {
        float a = 0.f, b = 0.f;
#pragma unroll
        for (int k = 0; k < 8; k++) { a += shl[k]; b += shr[k]; }
        g_loss_part[blockIdx.x] = a;
        g_rate_part[blockIdx.x] = b;
    }
}

// ---------------- exact resolver: fp64 z from inputs for ambiguous rows ----------------
__global__ __launch_bounds__(256) void exact_fix_kernel(
    const float* __restrict__ embed, const float* __restrict__ pre_w,
    const float* __restrict__ pre_b, const float* __restrict__ cb,
    float* __restrict__ out_idx, int wr)
{
    __shared__ float  es[H_DIM];
    __shared__ double zs[D_DIM];
    __shared__ float  cand_v[128];
    __shared__ int    cand_i[128];
    __shared__ float  s_amin;
    __shared__ double wv[8];
    __shared__ int    wi[8];
    int tid = threadIdx.x, lane = tid & 31, wid = tid >> 5;
    int nab = g_amb_count;

    for (int it = blockIdx.x; it < nab; it += gridDim.x) {
        int row = g_amb_rows[it];
        for (int k = tid; k < H_DIM; k += 256) es[k] = embed[(size_t)row * H_DIM + k];
        if (tid < 32) {
            float4 tv = g_tv4[(size_t)row * 32 + tid];
            int4  ti  = g_ti4[(size_t)row * 32 + tid];
            cand_v[tid * 4 + 0] = tv.x; cand_i[tid * 4 + 0] = ti.x;
            cand_v[tid * 4 + 1] = tv.y; cand_i[tid * 4 + 1] = ti.y;
            cand_v[tid * 4 + 2] = tv.z; cand_i[tid * 4 + 2] = ti.z;
            cand_v[tid * 4 + 3] = tv.w; cand_i[tid * 4 + 3] = ti.w;
            float m = tv.x;
#pragma unroll
            for (int o = 16; o; o >>= 1) m = fminf(m, __shfl_xor_sync(0xffffffffu, m, o));
            if (tid == 0) s_amin = m;
        }
        __syncthreads();
        {
            const float* wrow = pre_w + (size_t)tid * H_DIM;
            double s = (double)pre_b[tid];
            for (int k = 0; k < H_DIM; k++) s += (double)es[k] * (double)wrow[k];
            zs[tid] = s;
        }
        __syncthreads();
        float thr = s_amin + 0.25f;
        double bv = 1e300; int bi = 0x7fffffff;
        for (int j = wid; j < 128; j += 8) {
            if (cand_v[j] > thr) continue;
            int code = cand_i[j];
            const float* cr = cb + (size_t)code * D_DIM;
            double s = 0.0;
#pragma unroll
            for (int k = 0; k < 8; k++) s += zs[k * 32 + lane] * (double)cr[k * 32 + lane];
#pragma unroll
            for (int o = 16; o; o >>= 1) s += __shfl_xor_sync(0xffffffffu, s, o);
            double sc = g_cnormd[code] - 2.0 * s;
            if (sc < bv || (sc == bv && code < bi)) { bv = sc; bi = code; }
        }
        if (lane == 0) { wv[wid] = bv; wi[wid] = bi; }
        __syncthreads();
        if (tid == 0) {
            double fbv = 1e300; int fbi = 0x7fffffff;
#pragma unroll
            for (int k = 0; k < 8; k++) {
                if (wv[k] < fbv || (wv[k] == fbv && wi[k] < fbi)) { fbv = wv[k]; fbi = wi[k]; }
            }
            g_idx[row] = fbi;
            if (wr) out_idx[row] = (float)fbi;
        }
        __syncthreads();
    }
}

__global__ void final_kernel(float* __restrict__ out, int wr) {
    __shared__ float rl[1024], rr[1024];
    int t = threadIdx.x;
    float a = 0.f, b = 0.f;
    for (int k = t; k < 4096; k += 1024) { a += g_loss_part[k]; b += g_rate_part[k]; }
    rl[t] = a; rr[t] = b; __syncthreads();
    for (int s = 512; s; s >>= 1) {
        if (t < s) { rl[t] += rl[t + s]; rr[t] += rr[t + s]; }
        __syncthreads();
    }
    if (t == 0 && wr) {
        out[0] = rr[0] / 0.69314718055994530942f;
        out[1] = 1.25f * rl[0] / (float)((size_t)N_TOK * D_DIM);
    }
}

// ---------------- host launcher ----------------
extern "C" void kernel_launch(void* const* d_in, const int* in_sizes, int n_in,
                              void* d_out, int out_size) {
    const float* embed  = (const float*)d_in[0];
    const float* pre_w  = (const float*)d_in[1];
    const float* pre_b  = (const float*)d_in[2];
    const float* cb     = (const float*)d_in[3];
    const float* post_w = (const float*)d_in[4];
    const float* post_b = (const float*)d_in[5];
    const float* prior  = (const float*)d_in[6];
    float* out = (float*)d_out;

    float* zptr; cudaGetSymbolAddress((void**)&zptr, g_zf);
    int*   iptr; cudaGetSymbolAddress((void**)&iptr, g_idx);
    __half *ehi, *elo, *pwhi, *pwlo, *cbhi, *cblo, *pohi, *polo, *zhi, *zlo;
    cudaGetSymbolAddress((void**)&ehi,  g_ehi);  cudaGetSymbolAddress((void**)&elo,  g_elo);
    cudaGetSymbolAddress((void**)&pwhi, g_pwhi); cudaGetSymbolAddress((void**)&pwlo, g_pwlo);
    cudaGetSymbolAddress((void**)&cbhi, g_cbhi); cudaGetSymbolAddress((void**)&cblo, g_cblo);
    cudaGetSymbolAddress((void**)&pohi, g_pohi); cudaGetSymbolAddress((void**)&polo, g_polo);
    cudaGetSymbolAddress((void**)&zhi,  g_zhi);  cudaGetSymbolAddress((void**)&zlo,  g_zlo);

    const int SMEM = 2 * STAGE_BYTES;   // 81920 B
    cudaFuncSetAttribute(gemm_mm<0>, cudaFuncAttributeMaxDynamicSharedMemorySize, SMEM);
    cudaFuncSetAttribute(gemm_mm<1>, cudaFuncAttributeMaxDynamicSharedMemorySize, SMEM);
    cudaFuncSetAttribute(gemm_mm<2>, cudaFuncAttributeMaxDynamicSharedMemorySize, SMEM);

    // preconversion to split fp16 (hi/lo)
    split2h_kernel<<<(N_TOK * H_DIM / 4 + 255) / 256, 256>>>(embed, ehi, elo, N_TOK * H_DIM / 4);
    split2h_kernel<<<(D_DIM * H_DIM / 4 + 255) / 256, 256>>>(pre_w, pwhi, pwlo, D_DIM * H_DIM / 4);
    split2h_kernel<<<(K_CODE * D_DIM / 4 + 255) / 256, 256>>>(cb, cbhi, cblo, K_CODE * D_DIM / 4);
    split2h_kernel<<<(H_DIM * D_DIM / 4 + 255) / 256, 256>>>(post_w, pohi, polo, H_DIM * D_DIM / 4);
    cnorm_kernel<<<K_CODE / 8, 256>>>(cb);
    lse_kernel<<<1, 1024>>>(prior);

    // GEMM1: z = embed @ pre_w^T + pre_b   (M=32768, N=256, K=2048); also emit z hi/lo
    gemm_mm<1><<<dim3(D_DIM / 128, N_TOK / 128), 256, SMEM>>>(
        ehi, elo, pwhi, pwlo, H_DIM, H_DIM, H_DIM / 32, pre_b, zptr, D_DIM, nullptr);

    // distances: per-chunk top-4 of ||c||^2 - 2 z.c   (M=32768, N=4096, K=256)
    gemm_mm<2><<<dim3(K_CODE / 128, N_TOK / 128), 256, SMEM>>>(
        zhi, zlo, cbhi, cblo, D_DIM, D_DIM, D_DIM / 32, nullptr, nullptr, 0, nullptr);

    long long need = (long long)N_TOK * H_DIM + N_TOK + 2;
    int full = ((long long)out_size >= need) ? 1 : 0;

    // fp64 argmin on z~ + ambiguity flags + loss/rate partials + index output
    rescue_kernel<<<N_TOK / 8, 256>>>(cb, prior, out + (size_t)N_TOK * H_DIM, full);

    // exact fp64-z re-resolution for ambiguous rows (corrects g_idx before GEMM3)
    exact_fix_kernel<<<128, 256>>>(embed, pre_w, pre_b, cb, out + (size_t)N_TOK * H_DIM, full);

    // GEMM3: embed_hat = codebook[idx] @ post_w^T + post_b  (M=32768, N=2048, K=256)
    gemm_mm<0><<<dim3(H_DIM / 128, N_TOK / 128), 256, SMEM>>>(
        cbhi, cblo, pohi, polo, D_DIM, D_DIM, D_DIM / 32, post_b, out, H_DIM, iptr);

    final_kernel<<<1, 1024>>>(out + (size_t)N_TOK * H_DIM + N_TOK, full);
}